// round 15
// baseline (speedup 1.0000x reference)
#include <cuda_runtime.h>
#include <cuda_fp16.h>
#include <math.h>
#include <stdint.h>

// Shapes: B=16, N=1024 (32x32), C=512, GROUPS=32
__device__ __half g_xn [16384u*512u];
__device__ __half g_w  [5u*512u*512u];     // wq|wk|wvp|wv|wp fp16 (wvp computed on-device)
__device__ float  g_b  [3u*512u];          // bq|bk|bvp1 (bvp1 = bv@wp)
__device__ __half g_qkv[3u*16384u*512u];   // q|k|vp
__device__ __half g_p  [16u*1024u*1024u];  // exp(scores) fp16 (unnormalized)
__device__ float  g_rs [16384u];           // per-row sum of exp(scores)

__device__ __forceinline__ void mma_f16(float* d, const uint32_t* a, const uint32_t* b) {
    asm volatile(
        "mma.sync.aligned.m16n8k16.row.col.f32.f16.f16.f32 "
        "{%0,%1,%2,%3}, {%4,%5,%6,%7}, {%8,%9}, {%0,%1,%2,%3};"
        : "+f"(d[0]), "+f"(d[1]), "+f"(d[2]), "+f"(d[3])
        : "r"(a[0]), "r"(a[1]), "r"(a[2]), "r"(a[3]), "r"(b[0]), "r"(b[1]));
}
// .ca: keep lines in L1 — tiles are shared across CTAs (B across grid-y, A across grid-x)
__device__ __forceinline__ void cp16(uint32_t dst, const void* src) {
    asm volatile("cp.async.ca.shared.global [%0], [%1], 16;" :: "r"(dst), "l"(src));
}
__device__ __forceinline__ void cp_commit() {
    asm volatile("cp.async.commit_group;" ::: "memory");
}
template<int N> __device__ __forceinline__ void cp_wait() {
    asm volatile("cp.async.wait_group %0;" :: "n"(N) : "memory");
}
__device__ __forceinline__ void ldm_x4(uint32_t* r, uint32_t a) {
    asm volatile("ldmatrix.sync.aligned.m8n8.x4.shared.b16 {%0,%1,%2,%3}, [%4];"
                 : "=r"(r[0]), "=r"(r[1]), "=r"(r[2]), "=r"(r[3]) : "r"(a));
}
__device__ __forceinline__ void ldm_x4_t(uint32_t* r, uint32_t a) {
    asm volatile("ldmatrix.sync.aligned.m8n8.x4.trans.shared.b16 {%0,%1,%2,%3}, [%4];"
                 : "=r"(r[0]), "=r"(r[1]), "=r"(r[2]), "=r"(r[3]) : "r"(a));
}

// ---------------- fp16 mma.sync GEMM: 128x128 tile, BK=64, 3-stage, interleaved cp ----------------
// (R12 mainloop — validated; DO NOT TOUCH.)
// TRANSB=1: B is [N,K] row-major (NT). TRANSB=0: B is [K,N] row-major (NN).
// EPI: 0 = plain; 1 = exp(alpha*acc) + atomic row-sum; 2 = scale by 1/rowsum (then bias/res).
#define APITCH 72
#define BPITCH 136
#define A_STG (128 * APITCH)
#define NSTG 3
template<int TRANSB, int HAS_BIAS, int HAS_RES, int OUT_HALF, int EPI>
__global__ void __launch_bounds__(256, 2) mma_gemm(
    const __half* __restrict__ A, const __half* __restrict__ B,
    const float* __restrict__ bias, const float* __restrict__ res,
    float* __restrict__ rowsum,
    void* __restrict__ Cv, int K, int lda, int ldb, int ldc, float alpha,
    size_t sA, size_t sB, size_t sC, int biasStride)
{
    extern __shared__ __align__(16) __half smem[];
    const int B_STG = TRANSB ? A_STG : (64 * BPITCH);
    __half* Asm = smem;
    __half* Bsm = smem + NSTG * A_STG;

    const int tid  = threadIdx.x;
    const int wid  = tid >> 5;
    const int lane = tid & 31;
    const int g = lane >> 2, c = lane & 3;
    const int warp_m = wid >> 2;
    const int warp_n = wid & 3;
    const int rowBase = blockIdx.y * 128;
    const int colBase = blockIdx.x * 128;
    A += (size_t)blockIdx.z * sA;
    B += (size_t)blockIdx.z * sB;
    if (HAS_BIAS) bias += (size_t)blockIdx.z * biasStride;
    if (EPI) rowsum += (size_t)blockIdx.z * 1024;
    __half* Ch = (__half*)Cv + (size_t)blockIdx.z * sC;
    float*  Cf = (float*)Cv  + (size_t)blockIdx.z * sC;
    if (HAS_RES) res += (size_t)blockIdx.z * sC;

    const uint32_t sAbase = (uint32_t)__cvta_generic_to_shared(Asm);
    const uint32_t sBbase = (uint32_t)__cvta_generic_to_shared(Bsm);

    // Persistent global src pointers (advance +64 halves per stage)
    const __half* pA[4];
    const __half* pB[4];
    uint32_t aoSm[4], boSm[4];
    {
        #pragma unroll
        for (int i = 0; i < 4; i++) {
            int idx = tid + 256 * i;
            int r = idx >> 3, seg = idx & 7;
            pA[i] = A + (size_t)(rowBase + r) * lda + seg * 8;
            aoSm[i] = (uint32_t)(r * APITCH + seg * 8) * 2u;
            if (TRANSB) {
                pB[i] = B + (size_t)(colBase + r) * ldb + seg * 8;
                boSm[i] = aoSm[i];
            } else {
                int kr = idx >> 4, seg2 = idx & 15;
                pB[i] = B + (size_t)kr * ldb + colBase + seg2 * 8;
                boSm[i] = (uint32_t)(kr * BPITCH + seg2 * 8) * 2u;
            }
        }
    }

    auto cp_stage = [&](int s) {
        const int buf = s % NSTG;
        const uint32_t ab = sAbase + (uint32_t)(buf * A_STG) * 2u;
        const uint32_t bb = sBbase + (uint32_t)(buf * B_STG) * 2u;
        #pragma unroll
        for (int i = 0; i < 4; i++) {
            cp16(ab + aoSm[i], pA[i]);
            pA[i] += 64;
        }
        if (TRANSB) {
            #pragma unroll
            for (int i = 0; i < 4; i++) {
                cp16(bb + boSm[i], pB[i]);
                pB[i] += 64;
            }
        } else {
            #pragma unroll
            for (int i = 0; i < 4; i++) {
                cp16(bb + boSm[i], pB[i]);
                pB[i] += (size_t)64 * ldb;
            }
        }
    };

    // Hoisted ldmatrix lane offsets (bytes)
    uint32_t aOff[4], bOff[2];
    #pragma unroll
    for (int mt = 0; mt < 4; mt++)
        aOff[mt] = (uint32_t)((warp_m * 64 + mt * 16 + (lane & 15)) * APITCH
                   + ((lane >> 4) & 1) * 8) * 2u;
    #pragma unroll
    for (int ntp = 0; ntp < 2; ntp++) {
        if (TRANSB)
            bOff[ntp] = (uint32_t)((warp_n * 32 + ntp * 16 + (lane & 15)) * APITCH
                        + ((lane >> 4) & 1) * 8) * 2u;
        else
            bOff[ntp] = (uint32_t)((lane & 15) * BPITCH + warp_n * 32 + ntp * 16
                        + ((lane >> 4) & 1) * 8) * 2u;
    }

    float acc[4][4][4] = {};
    const int nStages = K >> 6;
    cp_stage(0); cp_commit();
    cp_stage(1); cp_commit();

    for (int s = 0; s < nStages; s++) {
        cp_wait<1>();
        __syncthreads();
        const bool pf = (s + 2 < nStages);
        const int buf  = s % NSTG;
        const int buf2 = (s + 2) % NSTG;
        const uint32_t sAb = sAbase + (uint32_t)(buf * A_STG) * 2u;
        const uint32_t sBb = sBbase + (uint32_t)(buf * B_STG) * 2u;
        const uint32_t ab2 = sAbase + (uint32_t)(buf2 * A_STG) * 2u;
        const uint32_t bb2 = sBbase + (uint32_t)(buf2 * B_STG) * 2u;
        #pragma unroll
        for (int ks = 0; ks < 4; ks++) {
            uint32_t af[4][4];
            #pragma unroll
            for (int mt = 0; mt < 4; mt++)
                ldm_x4(af[mt], sAb + aOff[mt] + ks * 32);
            uint32_t bf[4][2];
            #pragma unroll
            for (int ntp = 0; ntp < 2; ntp++) {
                uint32_t r[4];
                if (TRANSB) {
                    ldm_x4(r, sBb + bOff[ntp] + ks * 32);
                    bf[2*ntp][0] = r[0]; bf[2*ntp][1] = r[2];
                    bf[2*ntp+1][0] = r[1]; bf[2*ntp+1][1] = r[3];
                } else {
                    ldm_x4_t(r, sBb + bOff[ntp] + ks * (16 * BPITCH * 2));
                    bf[2*ntp][0] = r[0]; bf[2*ntp][1] = r[1];
                    bf[2*ntp+1][0] = r[2]; bf[2*ntp+1][1] = r[3];
                }
            }
            // Interleaved prefetch for stage s+2: 2 cp16 per k-slice (after LDSMs)
            if (pf) {
                cp16(ab2 + aoSm[ks], pA[ks]);
                pA[ks] += 64;
                cp16(bb2 + boSm[ks], pB[ks]);
                if (TRANSB) pB[ks] += 64; else pB[ks] += (size_t)64 * ldb;
            }
            #pragma unroll
            for (int mt = 0; mt < 4; mt++)
                #pragma unroll
                for (int nt = 0; nt < 4; nt++)
                    mma_f16(acc[mt][nt], af[mt], bf[nt]);
        }
        cp_commit();   // one group per stage (possibly empty) keeps accounting exact
    }

    // Epilogue: order = alpha, EPI2 rowsum-scale, bias, residual
    #pragma unroll
    for (int mt = 0; mt < 4; mt++) {
        const int row0 = rowBase + warp_m * 64 + mt * 16 + g;
        float rp0 = 0.f, rp1 = 0.f;
        float inv0 = 1.f, inv1 = 1.f;
        if (EPI == 2) {
            inv0 = 1.f / rowsum[row0 & 1023];
            inv1 = 1.f / rowsum[(row0 + 8) & 1023];
        }
        #pragma unroll
        for (int nt = 0; nt < 4; nt++) {
            const int col = colBase + warp_n * 32 + nt * 8 + 2 * c;
            float v0 = acc[mt][nt][0] * alpha, v1 = acc[mt][nt][1] * alpha;
            float v2 = acc[mt][nt][2] * alpha, v3 = acc[mt][nt][3] * alpha;
            if (EPI == 1) {
                v0 = __expf(v0); v1 = __expf(v1);
                v2 = __expf(v2); v3 = __expf(v3);
                rp0 += v0 + v1; rp1 += v2 + v3;
            }
            if (EPI == 2) { v0 *= inv0; v1 *= inv0; v2 *= inv1; v3 *= inv1; }
            if (HAS_BIAS) {
                float b0 = bias[col], b1 = bias[col + 1];
                v0 += b0; v1 += b1; v2 += b0; v3 += b1;
            }
            if (HAS_RES) {
                float2 r0 = *(const float2*)(res + (size_t)row0 * ldc + col);
                float2 r1 = *(const float2*)(res + (size_t)(row0 + 8) * ldc + col);
                v0 += r0.x; v1 += r0.y; v2 += r1.x; v3 += r1.y;
            }
            if (OUT_HALF) {
                *(__half2*)(Ch + (size_t)row0 * ldc + col)       = __floats2half2_rn(v0, v1);
                *(__half2*)(Ch + (size_t)(row0 + 8) * ldc + col) = __floats2half2_rn(v2, v3);
            } else {
                *(float2*)(Cf + (size_t)row0 * ldc + col)       = make_float2(v0, v1);
                *(float2*)(Cf + (size_t)(row0 + 8) * ldc + col) = make_float2(v2, v3);
            }
        }
        if (EPI == 1) {
            rp0 += __shfl_xor_sync(0xffffffffu, rp0, 1);
            rp0 += __shfl_xor_sync(0xffffffffu, rp0, 2);
            rp1 += __shfl_xor_sync(0xffffffffu, rp1, 1);
            rp1 += __shfl_xor_sync(0xffffffffu, rp1, 2);
            if (c == 0) {
                atomicAdd(&rowsum[row0 & 1023], rp0);
                atomicAdd(&rowsum[(row0 + 8) & 1023], rp1);
            }
        }
    }
}

// ---------------- GroupNorm + fused init: weight convert, bq/bk copy, bvp1 GEMV, rowsum zero ----------------
// W layout: [wq|wk|(wvp slot)|wv|wp]; GN writes wq->0, wk->1, wv->3, wp->4.
__global__ void groupnorm_kernel(const float* __restrict__ x,
                                 const float* __restrict__ gamma,
                                 const float* __restrict__ beta,
                                 __half* __restrict__ out,
                                 const float* __restrict__ wq, const float* __restrict__ wk,
                                 const float* __restrict__ wv, const float* __restrict__ wp,
                                 const float* __restrict__ bq, const float* __restrict__ bk,
                                 const float* __restrict__ bv,
                                 __half* __restrict__ W, float* __restrict__ Bc,
                                 float* __restrict__ rs) {
    const int gt = blockIdx.x * 256 + threadIdx.x;   // 0..131071
    {
        #pragma unroll
        for (int j = 0; j < 2; j++) {
            int idx4 = gt * 2 + j;
            int w_id = idx4 >> 16;                  // 0..3
            int off  = (idx4 & 65535) * 4;
            const float* src = (w_id == 0) ? wq : (w_id == 1) ? wk : (w_id == 2) ? wv : wp;
            int slot = (w_id < 2) ? w_id : (w_id + 1);   // wv->3, wp->4
            float4 v = *(const float4*)(src + off);
            __half2* dst = (__half2*)(W + (size_t)slot * 262144u + off);
            dst[0] = __floats2half2_rn(v.x, v.y);
            dst[1] = __floats2half2_rn(v.z, v.w);
        }
        if (gt < 256) {   // bq, bk float4 copies
            int j = gt >> 7, off = (gt & 127) * 4;
            const float* bs = (j == 0) ? bq : bk;
            *(float4*)(Bc + j * 512 + off) = *(const float4*)(bs + off);
        }
        if (gt >= 512 && gt < 1024) {   // bvp1[j] = sum_i bv[i] * wp[i][j] (blocks 2,3)
            const int j = gt - 512;
            float s = 0.f;
            #pragma unroll 8
            for (int i = 0; i < 512; i++)
                s += bv[i] * wp[i * 512 + j];
            Bc[2 * 512 + j] = s;
        }
        if (gt < 4096)
            *(float4*)(rs + gt * 4) = make_float4(0.f, 0.f, 0.f, 0.f);
    }
    const int b = blockIdx.x >> 5;
    const int g = blockIdx.x & 31;
    const float* xb = x + (size_t)b * 1024 * 512 + g * 16;
    float s1 = 0.f, s2 = 0.f;
    for (int i = threadIdx.x; i < 4096; i += 256) {
        int n = i >> 2, q = i & 3;
        float4 v = *(const float4*)(xb + (size_t)n * 512 + q * 4);
        s1 += v.x + v.y + v.z + v.w;
        s2 += v.x * v.x + v.y * v.y + v.z * v.z + v.w * v.w;
    }
    __shared__ float r1[256], r2[256];
    r1[threadIdx.x] = s1; r2[threadIdx.x] = s2;
    __syncthreads();
    for (int off = 128; off > 0; off >>= 1) {
        if (threadIdx.x < off) {
            r1[threadIdx.x] += r1[threadIdx.x + off];
            r2[threadIdx.x] += r2[threadIdx.x + off];
        }
        __syncthreads();
    }
    const float mean = r1[0] * (1.f / 16384.f);
    const float var  = r2[0] * (1.f / 16384.f) - mean * mean;
    const float inv  = rsqrtf(var + 1e-3f);
    __half* ob = out + (size_t)b * 1024 * 512 + g * 16;
    for (int i = threadIdx.x; i < 4096; i += 256) {
        int n = i >> 2, q = i & 3;
        int ch = g * 16 + q * 4;
        float4 v = *(const float4*)(xb + (size_t)n * 512 + q * 4);
        float o0 = (v.x - mean) * inv * gamma[ch + 0] + beta[ch + 0];
        float o1 = (v.y - mean) * inv * gamma[ch + 1] + beta[ch + 1];
        float o2 = (v.z - mean) * inv * gamma[ch + 2] + beta[ch + 2];
        float o3 = (v.w - mean) * inv * gamma[ch + 3] + beta[ch + 3];
        __half2* dst = (__half2*)(ob + (size_t)n * 512 + q * 4);
        dst[0] = __floats2half2_rn(o0, o1);
        dst[1] = __floats2half2_rn(o2, o3);
    }
}

extern "C" void kernel_launch(void* const* d_in, const int* in_sizes, int n_in,
                              void* d_out, int out_size) {
    const float* x     = (const float*)d_in[0];
    const float* gamma = (const float*)d_in[1];
    const float* beta  = (const float*)d_in[2];
    const float* wq    = (const float*)d_in[3];
    const float* bq    = (const float*)d_in[4];
    const float* wk    = (const float*)d_in[5];
    const float* bk    = (const float*)d_in[6];
    const float* wv    = (const float*)d_in[7];
    const float* bv    = (const float*)d_in[8];
    const float* wp    = (const float*)d_in[9];
    const float* bp    = (const float*)d_in[10];
    float* out = (float*)d_out;

    __half *xn, *W, *qkv, *p;
    float *Bc, *rs;
    cudaGetSymbolAddress((void**)&xn,  g_xn);
    cudaGetSymbolAddress((void**)&W,   g_w);
    cudaGetSymbolAddress((void**)&Bc,  g_b);
    cudaGetSymbolAddress((void**)&qkv, g_qkv);
    cudaGetSymbolAddress((void**)&p,   g_p);
    cudaGetSymbolAddress((void**)&rs,  g_rs);

    const int SMEM_NT = NSTG * (A_STG + A_STG) * 2;            // 110592
    const int SMEM_NN = NSTG * (A_STG + 64 * BPITCH) * 2;      // 107520
    cudaFuncSetAttribute(mma_gemm<0,0,0,1,0>, cudaFuncAttributeMaxDynamicSharedMemorySize, SMEM_NN);
    cudaFuncSetAttribute(mma_gemm<0,1,0,1,0>, cudaFuncAttributeMaxDynamicSharedMemorySize, SMEM_NN);
    cudaFuncSetAttribute(mma_gemm<1,0,0,1,1>, cudaFuncAttributeMaxDynamicSharedMemorySize, SMEM_NT);
    cudaFuncSetAttribute(mma_gemm<0,1,1,0,2>, cudaFuncAttributeMaxDynamicSharedMemorySize, SMEM_NN);

    const float scale = 0.044194173824159216f;  // 512^-0.5
    const size_t sQK = 1024u * 512u;
    const size_t sS  = 1024u * 1024u;
    const size_t kOff = 16u * sQK;
    const size_t vOff = 32u * sQK;
    const size_t WS = 262144u;   // one 512x512 fp16 slot

    // 1) GroupNorm -> fp16 xn, fused: weight convert (0,1,3,4), bq/bk, bvp1 GEMV, rs zero
    groupnorm_kernel<<<512, 256>>>(x, gamma, beta, xn,
                                   wq, wk, wv, wp, bq, bk, bv, W, Bc, rs);
    // 2) wvp = wv @ wp (fp16 GEMM) -> W slot 2
    mma_gemm<0,0,0,1,0><<<dim3(4, 4, 1), 256, SMEM_NN>>>(
        W + 3u * WS, W + 4u * WS, nullptr, nullptr, nullptr, W + 2u * WS,
        512, 512, 512, 512, 1.f, 0, 0, 0, 0);
    // 3) fused Q|K|VP projection: z=2 computes vp = xn@wvp + bvp1
    mma_gemm<0,1,0,1,0><<<dim3(4, 128, 3), 256, SMEM_NN>>>(
        xn, W, Bc, nullptr, nullptr, qkv, 512, 512, 512, 512, 1.f,
        0, WS, kOff, 512);
    // 4) P_unnorm = exp(scale * Q @ K^T), rowsum accumulated (batched NT)
    mma_gemm<1,0,0,1,1><<<dim3(8, 8, 16), 256, SMEM_NT>>>(
        qkv, qkv + kOff, nullptr, nullptr, rs, p, 512, 512, 512, 1024, scale,
        sQK, sQK, sS, 0);
    // 5) out = (P @ vp)/rs + bp + x  (batched NN, fp32 out, final)
    mma_gemm<0,1,1,0,2><<<dim3(4, 8, 16), 256, SMEM_NN>>>(
        p, qkv + vOff, bp, x, rs, out, 1024, 1024, 512, 512, 1.f,
        sS, sQK, sQK, 0);
}

// round 16
// speedup vs baseline: 1.0330x; 1.0330x over previous
#include <cuda_runtime.h>
#include <cuda_fp16.h>
#include <math.h>
#include <stdint.h>

// Shapes: B=16, N=1024 (32x32), C=512, GROUPS=32
__device__ __half g_xn [16384u*512u];
__device__ __half g_w  [5u*512u*512u];     // wq|wk|wvp|wv|wp fp16 (wvp computed on-device)
__device__ float  g_b  [3u*512u];          // bq|bk|bvp1 (bvp1 = bv@wp)
__device__ __half g_qkv[3u*16384u*512u];   // q|k|vp
__device__ __half g_p  [16u*1024u*1024u];  // exp(scores) fp16 (unnormalized)
__device__ float  g_rs [16384u];           // per-row sum of exp(scores)

__device__ __forceinline__ void mma_f16(float* d, const uint32_t* a, const uint32_t* b) {
    asm volatile(
        "mma.sync.aligned.m16n8k16.row.col.f32.f16.f16.f32 "
        "{%0,%1,%2,%3}, {%4,%5,%6,%7}, {%8,%9}, {%0,%1,%2,%3};"
        : "+f"(d[0]), "+f"(d[1]), "+f"(d[2]), "+f"(d[3])
        : "r"(a[0]), "r"(a[1]), "r"(a[2]), "r"(a[3]), "r"(b[0]), "r"(b[1]));
}
// .cg: L1-bypass direct-to-smem — validated; .ca regressed (L1 fill path fights LDSM)
__device__ __forceinline__ void cp16(uint32_t dst, const void* src) {
    asm volatile("cp.async.cg.shared.global [%0], [%1], 16;" :: "r"(dst), "l"(src));
}
__device__ __forceinline__ void cp_commit() {
    asm volatile("cp.async.commit_group;" ::: "memory");
}
template<int N> __device__ __forceinline__ void cp_wait() {
    asm volatile("cp.async.wait_group %0;" :: "n"(N) : "memory");
}
__device__ __forceinline__ void ldm_x4(uint32_t* r, uint32_t a) {
    asm volatile("ldmatrix.sync.aligned.m8n8.x4.shared.b16 {%0,%1,%2,%3}, [%4];"
                 : "=r"(r[0]), "=r"(r[1]), "=r"(r[2]), "=r"(r[3]) : "r"(a));
}
__device__ __forceinline__ void ldm_x4_t(uint32_t* r, uint32_t a) {
    asm volatile("ldmatrix.sync.aligned.m8n8.x4.trans.shared.b16 {%0,%1,%2,%3}, [%4];"
                 : "=r"(r[0]), "=r"(r[1]), "=r"(r[2]), "=r"(r[3]) : "r"(a));
}

// ---------------- fp16 mma.sync GEMM: 128x128 tile, BK=64, 3-stage, interleaved cp ----------------
// (R12 mainloop — validated; DO NOT TOUCH.)
// TRANSB=1: B is [N,K] row-major (NT). TRANSB=0: B is [K,N] row-major (NN).
// EPI: 0 = plain; 1 = exp(alpha*acc) + atomic row-sum; 2 = scale by 1/rowsum (then bias/res).
#define APITCH 72
#define BPITCH 136
#define A_STG (128 * APITCH)
#define NSTG 3
template<int TRANSB, int HAS_BIAS, int HAS_RES, int OUT_HALF, int EPI>
__global__ void __launch_bounds__(256, 2) mma_gemm(
    const __half* __restrict__ A, const __half* __restrict__ B,
    const float* __restrict__ bias, const float* __restrict__ res,
    float* __restrict__ rowsum,
    void* __restrict__ Cv, int K, int lda, int ldb, int ldc, float alpha,
    size_t sA, size_t sB, size_t sC, int biasStride)
{
    extern __shared__ __align__(16) __half smem[];
    const int B_STG = TRANSB ? A_STG : (64 * BPITCH);
    __half* Asm = smem;
    __half* Bsm = smem + NSTG * A_STG;

    const int tid  = threadIdx.x;
    const int wid  = tid >> 5;
    const int lane = tid & 31;
    const int g = lane >> 2, c = lane & 3;
    const int warp_m = wid >> 2;
    const int warp_n = wid & 3;
    const int rowBase = blockIdx.y * 128;
    const int colBase = blockIdx.x * 128;
    A += (size_t)blockIdx.z * sA;
    B += (size_t)blockIdx.z * sB;
    if (HAS_BIAS) bias += (size_t)blockIdx.z * biasStride;
    if (EPI) rowsum += (size_t)blockIdx.z * 1024;
    __half* Ch = (__half*)Cv + (size_t)blockIdx.z * sC;
    float*  Cf = (float*)Cv  + (size_t)blockIdx.z * sC;
    if (HAS_RES) res += (size_t)blockIdx.z * sC;

    const uint32_t sAbase = (uint32_t)__cvta_generic_to_shared(Asm);
    const uint32_t sBbase = (uint32_t)__cvta_generic_to_shared(Bsm);

    // Persistent global src pointers (advance +64 halves per stage)
    const __half* pA[4];
    const __half* pB[4];
    uint32_t aoSm[4], boSm[4];
    {
        #pragma unroll
        for (int i = 0; i < 4; i++) {
            int idx = tid + 256 * i;
            int r = idx >> 3, seg = idx & 7;
            pA[i] = A + (size_t)(rowBase + r) * lda + seg * 8;
            aoSm[i] = (uint32_t)(r * APITCH + seg * 8) * 2u;
            if (TRANSB) {
                pB[i] = B + (size_t)(colBase + r) * ldb + seg * 8;
                boSm[i] = aoSm[i];
            } else {
                int kr = idx >> 4, seg2 = idx & 15;
                pB[i] = B + (size_t)kr * ldb + colBase + seg2 * 8;
                boSm[i] = (uint32_t)(kr * BPITCH + seg2 * 8) * 2u;
            }
        }
    }

    auto cp_stage = [&](int s) {
        const int buf = s % NSTG;
        const uint32_t ab = sAbase + (uint32_t)(buf * A_STG) * 2u;
        const uint32_t bb = sBbase + (uint32_t)(buf * B_STG) * 2u;
        #pragma unroll
        for (int i = 0; i < 4; i++) {
            cp16(ab + aoSm[i], pA[i]);
            pA[i] += 64;
        }
        if (TRANSB) {
            #pragma unroll
            for (int i = 0; i < 4; i++) {
                cp16(bb + boSm[i], pB[i]);
                pB[i] += 64;
            }
        } else {
            #pragma unroll
            for (int i = 0; i < 4; i++) {
                cp16(bb + boSm[i], pB[i]);
                pB[i] += (size_t)64 * ldb;
            }
        }
    };

    // Hoisted ldmatrix lane offsets (bytes)
    uint32_t aOff[4], bOff[2];
    #pragma unroll
    for (int mt = 0; mt < 4; mt++)
        aOff[mt] = (uint32_t)((warp_m * 64 + mt * 16 + (lane & 15)) * APITCH
                   + ((lane >> 4) & 1) * 8) * 2u;
    #pragma unroll
    for (int ntp = 0; ntp < 2; ntp++) {
        if (TRANSB)
            bOff[ntp] = (uint32_t)((warp_n * 32 + ntp * 16 + (lane & 15)) * APITCH
                        + ((lane >> 4) & 1) * 8) * 2u;
        else
            bOff[ntp] = (uint32_t)((lane & 15) * BPITCH + warp_n * 32 + ntp * 16
                        + ((lane >> 4) & 1) * 8) * 2u;
    }

    float acc[4][4][4] = {};
    const int nStages = K >> 6;
    cp_stage(0); cp_commit();
    cp_stage(1); cp_commit();

    for (int s = 0; s < nStages; s++) {
        cp_wait<1>();
        __syncthreads();
        const bool pf = (s + 2 < nStages);
        const int buf  = s % NSTG;
        const int buf2 = (s + 2) % NSTG;
        const uint32_t sAb = sAbase + (uint32_t)(buf * A_STG) * 2u;
        const uint32_t sBb = sBbase + (uint32_t)(buf * B_STG) * 2u;
        const uint32_t ab2 = sAbase + (uint32_t)(buf2 * A_STG) * 2u;
        const uint32_t bb2 = sBbase + (uint32_t)(buf2 * B_STG) * 2u;
        #pragma unroll
        for (int ks = 0; ks < 4; ks++) {
            uint32_t af[4][4];
            #pragma unroll
            for (int mt = 0; mt < 4; mt++)
                ldm_x4(af[mt], sAb + aOff[mt] + ks * 32);
            uint32_t bf[4][2];
            #pragma unroll
            for (int ntp = 0; ntp < 2; ntp++) {
                uint32_t r[4];
                if (TRANSB) {
                    ldm_x4(r, sBb + bOff[ntp] + ks * 32);
                    bf[2*ntp][0] = r[0]; bf[2*ntp][1] = r[2];
                    bf[2*ntp+1][0] = r[1]; bf[2*ntp+1][1] = r[3];
                } else {
                    ldm_x4_t(r, sBb + bOff[ntp] + ks * (16 * BPITCH * 2));
                    bf[2*ntp][0] = r[0]; bf[2*ntp][1] = r[1];
                    bf[2*ntp+1][0] = r[2]; bf[2*ntp+1][1] = r[3];
                }
            }
            // Interleaved prefetch for stage s+2: 2 cp16 per k-slice (after LDSMs)
            if (pf) {
                cp16(ab2 + aoSm[ks], pA[ks]);
                pA[ks] += 64;
                cp16(bb2 + boSm[ks], pB[ks]);
                if (TRANSB) pB[ks] += 64; else pB[ks] += (size_t)64 * ldb;
            }
            #pragma unroll
            for (int mt = 0; mt < 4; mt++)
                #pragma unroll
                for (int nt = 0; nt < 4; nt++)
                    mma_f16(acc[mt][nt], af[mt], bf[nt]);
        }
        cp_commit();   // one group per stage (possibly empty) keeps accounting exact
    }

    // Epilogue: order = alpha, EPI2 rowsum-scale, bias, residual
    #pragma unroll
    for (int mt = 0; mt < 4; mt++) {
        const int row0 = rowBase + warp_m * 64 + mt * 16 + g;
        float rp0 = 0.f, rp1 = 0.f;
        float inv0 = 1.f, inv1 = 1.f;
        if (EPI == 2) {
            inv0 = 1.f / rowsum[row0 & 1023];
            inv1 = 1.f / rowsum[(row0 + 8) & 1023];
        }
        #pragma unroll
        for (int nt = 0; nt < 4; nt++) {
            const int col = colBase + warp_n * 32 + nt * 8 + 2 * c;
            float v0 = acc[mt][nt][0] * alpha, v1 = acc[mt][nt][1] * alpha;
            float v2 = acc[mt][nt][2] * alpha, v3 = acc[mt][nt][3] * alpha;
            if (EPI == 1) {
                v0 = __expf(v0); v1 = __expf(v1);
                v2 = __expf(v2); v3 = __expf(v3);
                rp0 += v0 + v1; rp1 += v2 + v3;
            }
            if (EPI == 2) { v0 *= inv0; v1 *= inv0; v2 *= inv1; v3 *= inv1; }
            if (HAS_BIAS) {
                float b0 = bias[col], b1 = bias[col + 1];
                v0 += b0; v1 += b1; v2 += b0; v3 += b1;
            }
            if (HAS_RES) {
                float2 r0 = *(const float2*)(res + (size_t)row0 * ldc + col);
                float2 r1 = *(const float2*)(res + (size_t)(row0 + 8) * ldc + col);
                v0 += r0.x; v1 += r0.y; v2 += r1.x; v3 += r1.y;
            }
            if (OUT_HALF) {
                *(__half2*)(Ch + (size_t)row0 * ldc + col)       = __floats2half2_rn(v0, v1);
                *(__half2*)(Ch + (size_t)(row0 + 8) * ldc + col) = __floats2half2_rn(v2, v3);
            } else {
                *(float2*)(Cf + (size_t)row0 * ldc + col)       = make_float2(v0, v1);
                *(float2*)(Cf + (size_t)(row0 + 8) * ldc + col) = make_float2(v2, v3);
            }
        }
        if (EPI == 1) {
            rp0 += __shfl_xor_sync(0xffffffffu, rp0, 1);
            rp0 += __shfl_xor_sync(0xffffffffu, rp0, 2);
            rp1 += __shfl_xor_sync(0xffffffffu, rp1, 1);
            rp1 += __shfl_xor_sync(0xffffffffu, rp1, 2);
            if (c == 0) {
                atomicAdd(&rowsum[row0 & 1023], rp0);
                atomicAdd(&rowsum[(row0 + 8) & 1023], rp1);
            }
        }
    }
}

// ---------------- GroupNorm + fused init: weight convert, bq/bk copy, bvp1 GEMV, rowsum zero ----------------
// W layout: [wq|wk|(wvp slot)|wv|wp]; GN writes wq->0, wk->1, wv->3, wp->4.
__global__ void groupnorm_kernel(const float* __restrict__ x,
                                 const float* __restrict__ gamma,
                                 const float* __restrict__ beta,
                                 __half* __restrict__ out,
                                 const float* __restrict__ wq, const float* __restrict__ wk,
                                 const float* __restrict__ wv, const float* __restrict__ wp,
                                 const float* __restrict__ bq, const float* __restrict__ bk,
                                 const float* __restrict__ bv,
                                 __half* __restrict__ W, float* __restrict__ Bc,
                                 float* __restrict__ rs) {
    const int gt = blockIdx.x * 256 + threadIdx.x;   // 0..131071
    {
        #pragma unroll
        for (int j = 0; j < 2; j++) {
            int idx4 = gt * 2 + j;
            int w_id = idx4 >> 16;                  // 0..3
            int off  = (idx4 & 65535) * 4;
            const float* src = (w_id == 0) ? wq : (w_id == 1) ? wk : (w_id == 2) ? wv : wp;
            int slot = (w_id < 2) ? w_id : (w_id + 1);   // wv->3, wp->4
            float4 v = *(const float4*)(src + off);
            __half2* dst = (__half2*)(W + (size_t)slot * 262144u + off);
            dst[0] = __floats2half2_rn(v.x, v.y);
            dst[1] = __floats2half2_rn(v.z, v.w);
        }
        if (gt < 256) {   // bq, bk float4 copies
            int j = gt >> 7, off = (gt & 127) * 4;
            const float* bs = (j == 0) ? bq : bk;
            *(float4*)(Bc + j * 512 + off) = *(const float4*)(bs + off);
        }
        if (gt >= 512 && gt < 1024) {   // bvp1[j] = sum_i bv[i] * wp[i][j] (blocks 2,3)
            const int j = gt - 512;
            float s = 0.f;
            #pragma unroll 8
            for (int i = 0; i < 512; i++)
                s += bv[i] * wp[i * 512 + j];
            Bc[2 * 512 + j] = s;
        }
        if (gt < 4096)
            *(float4*)(rs + gt * 4) = make_float4(0.f, 0.f, 0.f, 0.f);
    }
    const int b = blockIdx.x >> 5;
    const int g = blockIdx.x & 31;
    const float* xb = x + (size_t)b * 1024 * 512 + g * 16;
    float s1 = 0.f, s2 = 0.f;
    for (int i = threadIdx.x; i < 4096; i += 256) {
        int n = i >> 2, q = i & 3;
        float4 v = *(const float4*)(xb + (size_t)n * 512 + q * 4);
        s1 += v.x + v.y + v.z + v.w;
        s2 += v.x * v.x + v.y * v.y + v.z * v.z + v.w * v.w;
    }
    __shared__ float r1[256], r2[256];
    r1[threadIdx.x] = s1; r2[threadIdx.x] = s2;
    __syncthreads();
    for (int off = 128; off > 0; off >>= 1) {
        if (threadIdx.x < off) {
            r1[threadIdx.x] += r1[threadIdx.x + off];
            r2[threadIdx.x] += r2[threadIdx.x + off];
        }
        __syncthreads();
    }
    const float mean = r1[0] * (1.f / 16384.f);
    const float var  = r2[0] * (1.f / 16384.f) - mean * mean;
    const float inv  = rsqrtf(var + 1e-3f);
    __half* ob = out + (size_t)b * 1024 * 512 + g * 16;
    for (int i = threadIdx.x; i < 4096; i += 256) {
        int n = i >> 2, q = i & 3;
        int ch = g * 16 + q * 4;
        float4 v = *(const float4*)(xb + (size_t)n * 512 + q * 4);
        float o0 = (v.x - mean) * inv * gamma[ch + 0] + beta[ch + 0];
        float o1 = (v.y - mean) * inv * gamma[ch + 1] + beta[ch + 1];
        float o2 = (v.z - mean) * inv * gamma[ch + 2] + beta[ch + 2];
        float o3 = (v.w - mean) * inv * gamma[ch + 3] + beta[ch + 3];
        __half2* dst = (__half2*)(ob + (size_t)n * 512 + q * 4);
        dst[0] = __floats2half2_rn(o0, o1);
        dst[1] = __floats2half2_rn(o2, o3);
    }
}

extern "C" void kernel_launch(void* const* d_in, const int* in_sizes, int n_in,
                              void* d_out, int out_size) {
    const float* x     = (const float*)d_in[0];
    const float* gamma = (const float*)d_in[1];
    const float* beta  = (const float*)d_in[2];
    const float* wq    = (const float*)d_in[3];
    const float* bq    = (const float*)d_in[4];
    const float* wk    = (const float*)d_in[5];
    const float* bk    = (const float*)d_in[6];
    const float* wv    = (const float*)d_in[7];
    const float* bv    = (const float*)d_in[8];
    const float* wp    = (const float*)d_in[9];
    const float* bp    = (const float*)d_in[10];
    float* out = (float*)d_out;

    __half *xn, *W, *qkv, *p;
    float *Bc, *rs;
    cudaGetSymbolAddress((void**)&xn,  g_xn);
    cudaGetSymbolAddress((void**)&W,   g_w);
    cudaGetSymbolAddress((void**)&Bc,  g_b);
    cudaGetSymbolAddress((void**)&qkv, g_qkv);
    cudaGetSymbolAddress((void**)&p,   g_p);
    cudaGetSymbolAddress((void**)&rs,  g_rs);

    const int SMEM_NT = NSTG * (A_STG + A_STG) * 2;            // 110592
    const int SMEM_NN = NSTG * (A_STG + 64 * BPITCH) * 2;      // 107520
    cudaFuncSetAttribute(mma_gemm<0,0,0,1,0>, cudaFuncAttributeMaxDynamicSharedMemorySize, SMEM_NN);
    cudaFuncSetAttribute(mma_gemm<0,1,0,1,0>, cudaFuncAttributeMaxDynamicSharedMemorySize, SMEM_NN);
    cudaFuncSetAttribute(mma_gemm<1,0,0,1,1>, cudaFuncAttributeMaxDynamicSharedMemorySize, SMEM_NT);
    cudaFuncSetAttribute(mma_gemm<0,1,1,0,2>, cudaFuncAttributeMaxDynamicSharedMemorySize, SMEM_NN);

    const float scale = 0.044194173824159216f;  // 512^-0.5
    const size_t sQK = 1024u * 512u;
    const size_t sS  = 1024u * 1024u;
    const size_t kOff = 16u * sQK;
    const size_t vOff = 32u * sQK;
    const size_t WS = 262144u;   // one 512x512 fp16 slot

    // 1) GroupNorm -> fp16 xn, fused: weight convert (0,1,3,4), bq/bk, bvp1 GEMV, rs zero
    groupnorm_kernel<<<512, 256>>>(x, gamma, beta, xn,
                                   wq, wk, wv, wp, bq, bk, bv, W, Bc, rs);
    // 2) wvp = wv @ wp (fp16 GEMM) -> W slot 2
    mma_gemm<0,0,0,1,0><<<dim3(4, 4, 1), 256, SMEM_NN>>>(
        W + 3u * WS, W + 4u * WS, nullptr, nullptr, nullptr, W + 2u * WS,
        512, 512, 512, 512, 1.f, 0, 0, 0, 0);
    // 3) fused Q|K|VP projection: z=2 computes vp = xn@wvp + bvp1
    mma_gemm<0,1,0,1,0><<<dim3(4, 128, 3), 256, SMEM_NN>>>(
        xn, W, Bc, nullptr, nullptr, qkv, 512, 512, 512, 512, 1.f,
        0, WS, kOff, 512);
    // 4) P_unnorm = exp(scale * Q @ K^T), rowsum accumulated (batched NT)
    mma_gemm<1,0,0,1,1><<<dim3(8, 8, 16), 256, SMEM_NT>>>(
        qkv, qkv + kOff, nullptr, nullptr, rs, p, 512, 512, 512, 1024, scale,
        sQK, sQK, sS, 0);
    // 5) out = (P @ vp)/rs + bp + x  (batched NN, fp32 out, final)
    mma_gemm<0,1,1,0,2><<<dim3(4, 8, 16), 256, SMEM_NN>>>(
        p, qkv + vOff, bp, x, rs, out, 1024, 1024, 512, 512, 1.f,
        sS, sQK, sQK, 0);
}

// round 17
// speedup vs baseline: 1.0755x; 1.0412x over previous
#include <cuda_runtime.h>
#include <cuda_fp16.h>
#include <math.h>
#include <stdint.h>

// Shapes: B=16, N=1024 (32x32), C=512, GROUPS=32
__device__ __half g_xn [16384u*512u];
__device__ __half g_w  [5u*512u*512u];     // wq|wk|wvp|wv|wp fp16 (wvp computed on-device)
__device__ float  g_b  [3u*512u];          // bq|bk|bvp1 (bvp1 = bv@wp)
__device__ __half g_qkv[3u*16384u*512u];   // q|k|vp
__device__ __half g_p  [16u*1024u*1024u];  // exp(scores) fp16 (unnormalized)
__device__ float  g_rs [16384u];           // per-row sum of exp(scores)

__device__ __forceinline__ void mma_f16(float* d, const uint32_t* a, const uint32_t* b) {
    asm volatile(
        "mma.sync.aligned.m16n8k16.row.col.f32.f16.f16.f32 "
        "{%0,%1,%2,%3}, {%4,%5,%6,%7}, {%8,%9}, {%0,%1,%2,%3};"
        : "+f"(d[0]), "+f"(d[1]), "+f"(d[2]), "+f"(d[3])
        : "r"(a[0]), "r"(a[1]), "r"(a[2]), "r"(a[3]), "r"(b[0]), "r"(b[1]));
}
// .cg: L1-bypass direct-to-smem — validated; .ca regressed (L1 fill path fights LDSM)
__device__ __forceinline__ void cp16(uint32_t dst, const void* src) {
    asm volatile("cp.async.cg.shared.global [%0], [%1], 16;" :: "r"(dst), "l"(src));
}
__device__ __forceinline__ void cp_commit() {
    asm volatile("cp.async.commit_group;" ::: "memory");
}
template<int N> __device__ __forceinline__ void cp_wait() {
    asm volatile("cp.async.wait_group %0;" :: "n"(N) : "memory");
}
__device__ __forceinline__ void ldm_x4(uint32_t* r, uint32_t a) {
    asm volatile("ldmatrix.sync.aligned.m8n8.x4.shared.b16 {%0,%1,%2,%3}, [%4];"
                 : "=r"(r[0]), "=r"(r[1]), "=r"(r[2]), "=r"(r[3]) : "r"(a));
}
__device__ __forceinline__ void ldm_x4_t(uint32_t* r, uint32_t a) {
    asm volatile("ldmatrix.sync.aligned.m8n8.x4.trans.shared.b16 {%0,%1,%2,%3}, [%4];"
                 : "=r"(r[0]), "=r"(r[1]), "=r"(r[2]), "=r"(r[3]) : "r"(a));
}

// ---------------- fp16 mma.sync GEMM: 128x128 tile, BK=64, 3-stage, interleaved cp ----------------
// (R12 mainloop — validated; DO NOT TOUCH.)
// TRANSB=1: B is [N,K] row-major (NT). TRANSB=0: B is [K,N] row-major (NN).
// EPI: 0 = plain; 1 = exp(alpha*acc) + atomic row-sum; 2 = scale by 1/rowsum (then bias/res).
#define APITCH 72
#define BPITCH 136
#define A_STG (128 * APITCH)
#define NSTG 3
template<int TRANSB, int HAS_BIAS, int HAS_RES, int OUT_HALF, int EPI>
__global__ void __launch_bounds__(256, 2) mma_gemm(
    const __half* __restrict__ A, const __half* __restrict__ B,
    const float* __restrict__ bias, const float* __restrict__ res,
    float* __restrict__ rowsum,
    void* __restrict__ Cv, int K, int lda, int ldb, int ldc, float alpha,
    size_t sA, size_t sB, size_t sC, int biasStride)
{
    extern __shared__ __align__(16) __half smem[];
    const int B_STG = TRANSB ? A_STG : (64 * BPITCH);
    __half* Asm = smem;
    __half* Bsm = smem + NSTG * A_STG;

    const int tid  = threadIdx.x;
    const int wid  = tid >> 5;
    const int lane = tid & 31;
    const int g = lane >> 2, c = lane & 3;
    const int warp_m = wid >> 2;
    const int warp_n = wid & 3;
    const int rowBase = blockIdx.y * 128;
    const int colBase = blockIdx.x * 128;
    A += (size_t)blockIdx.z * sA;
    B += (size_t)blockIdx.z * sB;
    if (HAS_BIAS) bias += (size_t)blockIdx.z * biasStride;
    if (EPI) rowsum += (size_t)blockIdx.z * 1024;
    __half* Ch = (__half*)Cv + (size_t)blockIdx.z * sC;
    float*  Cf = (float*)Cv  + (size_t)blockIdx.z * sC;
    if (HAS_RES) res += (size_t)blockIdx.z * sC;

    const uint32_t sAbase = (uint32_t)__cvta_generic_to_shared(Asm);
    const uint32_t sBbase = (uint32_t)__cvta_generic_to_shared(Bsm);

    // Persistent global src pointers (advance +64 halves per stage)
    const __half* pA[4];
    const __half* pB[4];
    uint32_t aoSm[4], boSm[4];
    {
        #pragma unroll
        for (int i = 0; i < 4; i++) {
            int idx = tid + 256 * i;
            int r = idx >> 3, seg = idx & 7;
            pA[i] = A + (size_t)(rowBase + r) * lda + seg * 8;
            aoSm[i] = (uint32_t)(r * APITCH + seg * 8) * 2u;
            if (TRANSB) {
                pB[i] = B + (size_t)(colBase + r) * ldb + seg * 8;
                boSm[i] = aoSm[i];
            } else {
                int kr = idx >> 4, seg2 = idx & 15;
                pB[i] = B + (size_t)kr * ldb + colBase + seg2 * 8;
                boSm[i] = (uint32_t)(kr * BPITCH + seg2 * 8) * 2u;
            }
        }
    }

    auto cp_stage = [&](int s) {
        const int buf = s % NSTG;
        const uint32_t ab = sAbase + (uint32_t)(buf * A_STG) * 2u;
        const uint32_t bb = sBbase + (uint32_t)(buf * B_STG) * 2u;
        #pragma unroll
        for (int i = 0; i < 4; i++) {
            cp16(ab + aoSm[i], pA[i]);
            pA[i] += 64;
        }
        if (TRANSB) {
            #pragma unroll
            for (int i = 0; i < 4; i++) {
                cp16(bb + boSm[i], pB[i]);
                pB[i] += 64;
            }
        } else {
            #pragma unroll
            for (int i = 0; i < 4; i++) {
                cp16(bb + boSm[i], pB[i]);
                pB[i] += (size_t)64 * ldb;
            }
        }
    };

    // Hoisted ldmatrix lane offsets (bytes)
    uint32_t aOff[4], bOff[2];
    #pragma unroll
    for (int mt = 0; mt < 4; mt++)
        aOff[mt] = (uint32_t)((warp_m * 64 + mt * 16 + (lane & 15)) * APITCH
                   + ((lane >> 4) & 1) * 8) * 2u;
    #pragma unroll
    for (int ntp = 0; ntp < 2; ntp++) {
        if (TRANSB)
            bOff[ntp] = (uint32_t)((warp_n * 32 + ntp * 16 + (lane & 15)) * APITCH
                        + ((lane >> 4) & 1) * 8) * 2u;
        else
            bOff[ntp] = (uint32_t)((lane & 15) * BPITCH + warp_n * 32 + ntp * 16
                        + ((lane >> 4) & 1) * 8) * 2u;
    }

    float acc[4][4][4] = {};
    const int nStages = K >> 6;
    cp_stage(0); cp_commit();
    cp_stage(1); cp_commit();

    for (int s = 0; s < nStages; s++) {
        cp_wait<1>();
        __syncthreads();
        const bool pf = (s + 2 < nStages);
        const int buf  = s % NSTG;
        const int buf2 = (s + 2) % NSTG;
        const uint32_t sAb = sAbase + (uint32_t)(buf * A_STG) * 2u;
        const uint32_t sBb = sBbase + (uint32_t)(buf * B_STG) * 2u;
        const uint32_t ab2 = sAbase + (uint32_t)(buf2 * A_STG) * 2u;
        const uint32_t bb2 = sBbase + (uint32_t)(buf2 * B_STG) * 2u;
        #pragma unroll
        for (int ks = 0; ks < 4; ks++) {
            uint32_t af[4][4];
            #pragma unroll
            for (int mt = 0; mt < 4; mt++)
                ldm_x4(af[mt], sAb + aOff[mt] + ks * 32);
            uint32_t bf[4][2];
            #pragma unroll
            for (int ntp = 0; ntp < 2; ntp++) {
                uint32_t r[4];
                if (TRANSB) {
                    ldm_x4(r, sBb + bOff[ntp] + ks * 32);
                    bf[2*ntp][0] = r[0]; bf[2*ntp][1] = r[2];
                    bf[2*ntp+1][0] = r[1]; bf[2*ntp+1][1] = r[3];
                } else {
                    ldm_x4_t(r, sBb + bOff[ntp] + ks * (16 * BPITCH * 2));
                    bf[2*ntp][0] = r[0]; bf[2*ntp][1] = r[1];
                    bf[2*ntp+1][0] = r[2]; bf[2*ntp+1][1] = r[3];
                }
            }
            // Interleaved prefetch for stage s+2: 2 cp16 per k-slice (after LDSMs)
            if (pf) {
                cp16(ab2 + aoSm[ks], pA[ks]);
                pA[ks] += 64;
                cp16(bb2 + boSm[ks], pB[ks]);
                if (TRANSB) pB[ks] += 64; else pB[ks] += (size_t)64 * ldb;
            }
            #pragma unroll
            for (int mt = 0; mt < 4; mt++)
                #pragma unroll
                for (int nt = 0; nt < 4; nt++)
                    mma_f16(acc[mt][nt], af[mt], bf[nt]);
        }
        cp_commit();   // one group per stage (possibly empty) keeps accounting exact
    }

    // Epilogue: order = alpha, EPI2 rowsum-scale, bias, residual
    #pragma unroll
    for (int mt = 0; mt < 4; mt++) {
        const int row0 = rowBase + warp_m * 64 + mt * 16 + g;
        float rp0 = 0.f, rp1 = 0.f;
        float inv0 = 1.f, inv1 = 1.f;
        if (EPI == 2) {
            inv0 = 1.f / rowsum[row0 & 1023];
            inv1 = 1.f / rowsum[(row0 + 8) & 1023];
        }
        #pragma unroll
        for (int nt = 0; nt < 4; nt++) {
            const int col = colBase + warp_n * 32 + nt * 8 + 2 * c;
            float v0 = acc[mt][nt][0] * alpha, v1 = acc[mt][nt][1] * alpha;
            float v2 = acc[mt][nt][2] * alpha, v3 = acc[mt][nt][3] * alpha;
            if (EPI == 1) {
                v0 = __expf(v0); v1 = __expf(v1);
                v2 = __expf(v2); v3 = __expf(v3);
                rp0 += v0 + v1; rp1 += v2 + v3;
            }
            if (EPI == 2) { v0 *= inv0; v1 *= inv0; v2 *= inv1; v3 *= inv1; }
            if (HAS_BIAS) {
                float b0 = bias[col], b1 = bias[col + 1];
                v0 += b0; v1 += b1; v2 += b0; v3 += b1;
            }
            if (HAS_RES) {
                float2 r0 = *(const float2*)(res + (size_t)row0 * ldc + col);
                float2 r1 = *(const float2*)(res + (size_t)(row0 + 8) * ldc + col);
                v0 += r0.x; v1 += r0.y; v2 += r1.x; v3 += r1.y;
            }
            if (OUT_HALF) {
                *(__half2*)(Ch + (size_t)row0 * ldc + col)       = __floats2half2_rn(v0, v1);
                *(__half2*)(Ch + (size_t)(row0 + 8) * ldc + col) = __floats2half2_rn(v2, v3);
            } else {
                *(float2*)(Cf + (size_t)row0 * ldc + col)       = make_float2(v0, v1);
                *(float2*)(Cf + (size_t)(row0 + 8) * ldc + col) = make_float2(v2, v3);
            }
        }
        if (EPI == 1) {
            rp0 += __shfl_xor_sync(0xffffffffu, rp0, 1);
            rp0 += __shfl_xor_sync(0xffffffffu, rp0, 2);
            rp1 += __shfl_xor_sync(0xffffffffu, rp1, 1);
            rp1 += __shfl_xor_sync(0xffffffffu, rp1, 2);
            if (c == 0) {
                atomicAdd(&rowsum[row0 & 1023], rp0);
                atomicAdd(&rowsum[(row0 + 8) & 1023], rp1);
            }
        }
    }
}

// ---------------- GroupNorm + fused init + overlapped wvp GEMM ----------------
// Blocks 0..511:  GroupNorm + weight convert (slots 0,1,3,4) + bq/bk + bvp1 GEMV + rs zero.
// Blocks 512..767: wvp = wv @ wp (fp32 SIMT, 32x32 tiles) -> W slot 2. Reads fp32 inputs
// directly (no dependency on the conversions), so it overlaps GN inside one launch.
__global__ void groupnorm_kernel(const float* __restrict__ x,
                                 const float* __restrict__ gamma,
                                 const float* __restrict__ beta,
                                 __half* __restrict__ out,
                                 const float* __restrict__ wq, const float* __restrict__ wk,
                                 const float* __restrict__ wv, const float* __restrict__ wp,
                                 const float* __restrict__ bq, const float* __restrict__ bk,
                                 const float* __restrict__ bv,
                                 __half* __restrict__ W, float* __restrict__ Bc,
                                 float* __restrict__ rs) {
    if (blockIdx.x >= 512) {
        // ---- wvp tile: 256 blocks in a 16x16 grid of 32x32 tiles, K=512 ----
        __shared__ float Av[32][33], Bp[32][33];
        const int t  = blockIdx.x - 512;
        const int bi = (t >> 4) * 32;
        const int bj = (t & 15) * 32;
        const int tx = threadIdx.x & 15, ty = threadIdx.x >> 4;
        float a00 = 0.f, a01 = 0.f, a10 = 0.f, a11 = 0.f;
        for (int kb = 0; kb < 512; kb += 32) {
            for (int i = threadIdx.x; i < 1024; i += 256) {
                int r = i >> 5, cc = i & 31;
                Av[r][cc] = wv[(size_t)(bi + r) * 512 + kb + cc];
                Bp[r][cc] = wp[(size_t)(kb + r) * 512 + bj + cc];
            }
            __syncthreads();
            #pragma unroll
            for (int k = 0; k < 32; k++) {
                float a0 = Av[ty * 2][k],     a1 = Av[ty * 2 + 1][k];
                float b0 = Bp[k][tx * 2],     b1 = Bp[k][tx * 2 + 1];
                a00 += a0 * b0; a01 += a0 * b1;
                a10 += a1 * b0; a11 += a1 * b1;
            }
            __syncthreads();
        }
        __half* Wvp = W + 2u * 262144u;
        const int r0 = bi + ty * 2, c0 = bj + tx * 2;
        *(__half2*)(Wvp + (size_t)r0 * 512 + c0)       = __floats2half2_rn(a00, a01);
        *(__half2*)(Wvp + (size_t)(r0 + 1) * 512 + c0) = __floats2half2_rn(a10, a11);
        return;
    }
    const int gt = blockIdx.x * 256 + threadIdx.x;   // 0..131071
    {
        #pragma unroll
        for (int j = 0; j < 2; j++) {
            int idx4 = gt * 2 + j;
            int w_id = idx4 >> 16;                  // 0..3
            int off  = (idx4 & 65535) * 4;
            const float* src = (w_id == 0) ? wq : (w_id == 1) ? wk : (w_id == 2) ? wv : wp;
            int slot = (w_id < 2) ? w_id : (w_id + 1);   // wv->3, wp->4
            float4 v = *(const float4*)(src + off);
            __half2* dst = (__half2*)(W + (size_t)slot * 262144u + off);
            dst[0] = __floats2half2_rn(v.x, v.y);
            dst[1] = __floats2half2_rn(v.z, v.w);
        }
        if (gt < 256) {   // bq, bk float4 copies
            int j = gt >> 7, off = (gt & 127) * 4;
            const float* bs = (j == 0) ? bq : bk;
            *(float4*)(Bc + j * 512 + off) = *(const float4*)(bs + off);
        }
        if (gt >= 512 && gt < 1024) {   // bvp1[j] = sum_i bv[i] * wp[i][j]
            const int j = gt - 512;
            float s = 0.f;
            #pragma unroll 8
            for (int i = 0; i < 512; i++)
                s += bv[i] * wp[i * 512 + j];
            Bc[2 * 512 + j] = s;
        }
        if (gt < 4096)
            *(float4*)(rs + gt * 4) = make_float4(0.f, 0.f, 0.f, 0.f);
    }
    const int b = blockIdx.x >> 5;
    const int g = blockIdx.x & 31;
    const float* xb = x + (size_t)b * 1024 * 512 + g * 16;
    float s1 = 0.f, s2 = 0.f;
    for (int i = threadIdx.x; i < 4096; i += 256) {
        int n = i >> 2, q = i & 3;
        float4 v = *(const float4*)(xb + (size_t)n * 512 + q * 4);
        s1 += v.x + v.y + v.z + v.w;
        s2 += v.x * v.x + v.y * v.y + v.z * v.z + v.w * v.w;
    }
    __shared__ float r1[256], r2[256];
    r1[threadIdx.x] = s1; r2[threadIdx.x] = s2;
    __syncthreads();
    for (int off = 128; off > 0; off >>= 1) {
        if (threadIdx.x < off) {
            r1[threadIdx.x] += r1[threadIdx.x + off];
            r2[threadIdx.x] += r2[threadIdx.x + off];
        }
        __syncthreads();
    }
    const float mean = r1[0] * (1.f / 16384.f);
    const float var  = r2[0] * (1.f / 16384.f) - mean * mean;
    const float inv  = rsqrtf(var + 1e-3f);
    __half* ob = out + (size_t)b * 1024 * 512 + g * 16;
    for (int i = threadIdx.x; i < 4096; i += 256) {
        int n = i >> 2, q = i & 3;
        int ch = g * 16 + q * 4;
        float4 v = *(const float4*)(xb + (size_t)n * 512 + q * 4);
        float o0 = (v.x - mean) * inv * gamma[ch + 0] + beta[ch + 0];
        float o1 = (v.y - mean) * inv * gamma[ch + 1] + beta[ch + 1];
        float o2 = (v.z - mean) * inv * gamma[ch + 2] + beta[ch + 2];
        float o3 = (v.w - mean) * inv * gamma[ch + 3] + beta[ch + 3];
        __half2* dst = (__half2*)(ob + (size_t)n * 512 + q * 4);
        dst[0] = __floats2half2_rn(o0, o1);
        dst[1] = __floats2half2_rn(o2, o3);
    }
}

extern "C" void kernel_launch(void* const* d_in, const int* in_sizes, int n_in,
                              void* d_out, int out_size) {
    const float* x     = (const float*)d_in[0];
    const float* gamma = (const float*)d_in[1];
    const float* beta  = (const float*)d_in[2];
    const float* wq    = (const float*)d_in[3];
    const float* bq    = (const float*)d_in[4];
    const float* wk    = (const float*)d_in[5];
    const float* bk    = (const float*)d_in[6];
    const float* wv    = (const float*)d_in[7];
    const float* bv    = (const float*)d_in[8];
    const float* wp    = (const float*)d_in[9];
    const float* bp    = (const float*)d_in[10];
    float* out = (float*)d_out;

    __half *xn, *W, *qkv, *p;
    float *Bc, *rs;
    cudaGetSymbolAddress((void**)&xn,  g_xn);
    cudaGetSymbolAddress((void**)&W,   g_w);
    cudaGetSymbolAddress((void**)&Bc,  g_b);
    cudaGetSymbolAddress((void**)&qkv, g_qkv);
    cudaGetSymbolAddress((void**)&p,   g_p);
    cudaGetSymbolAddress((void**)&rs,  g_rs);

    const int SMEM_NT = NSTG * (A_STG + A_STG) * 2;            // 110592
    const int SMEM_NN = NSTG * (A_STG + 64 * BPITCH) * 2;      // 107520
    cudaFuncSetAttribute(mma_gemm<0,1,0,1,0>, cudaFuncAttributeMaxDynamicSharedMemorySize, SMEM_NN);
    cudaFuncSetAttribute(mma_gemm<1,0,0,1,1>, cudaFuncAttributeMaxDynamicSharedMemorySize, SMEM_NT);
    cudaFuncSetAttribute(mma_gemm<0,1,1,0,2>, cudaFuncAttributeMaxDynamicSharedMemorySize, SMEM_NN);

    const float scale = 0.044194173824159216f;  // 512^-0.5
    const size_t sQK = 1024u * 512u;
    const size_t sS  = 1024u * 1024u;
    const size_t kOff = 16u * sQK;
    const size_t vOff = 32u * sQK;
    const size_t WS = 262144u;   // one 512x512 fp16 slot

    // 1) GroupNorm + fused init (blocks 0..511) ∥ wvp = wv@wp (blocks 512..767)
    groupnorm_kernel<<<768, 256>>>(x, gamma, beta, xn,
                                   wq, wk, wv, wp, bq, bk, bv, W, Bc, rs);
    // 2) fused Q|K|VP projection: z=2 computes vp = xn@wvp + bvp1
    mma_gemm<0,1,0,1,0><<<dim3(4, 128, 3), 256, SMEM_NN>>>(
        xn, W, Bc, nullptr, nullptr, qkv, 512, 512, 512, 512, 1.f,
        0, WS, kOff, 512);
    // 3) P_unnorm = exp(scale * Q @ K^T), rowsum accumulated (batched NT)
    mma_gemm<1,0,0,1,1><<<dim3(8, 8, 16), 256, SMEM_NT>>>(
        qkv, qkv + kOff, nullptr, nullptr, rs, p, 512, 512, 512, 1024, scale,
        sQK, sQK, sS, 0);
    // 4) out = (P @ vp)/rs + bp + x  (batched NN, fp32 out, final)
    mma_gemm<0,1,1,0,2><<<dim3(4, 8, 16), 256, SMEM_NN>>>(
        p, qkv + vOff, bp, x, rs, out, 1024, 1024, 512, 512, 1.f,
        sS, sQK, sQK, 0);
}